// round 3
// baseline (speedup 1.0000x reference)
#include <cuda_runtime.h>
#include <cuda_bf16.h>

// ---------------- problem constants ----------------
#define AA        9
#define HH        128
#define WW        192
#define HW        (HH * WW)          // 24576
#define NTOT      (HW * AA)          // 221184
#define PRE_N     6000
#define POST_N    300
#define MASK_W    94                 // ceil(6000/64)
#define CAP       8192               // candidate capacity (power of 2 for bitonic)
#define HALF      4096
#define HIST_BITS 16
#define HIST_SZ   (1u << HIST_BITS)
#define NMS_TH    0.7f

// ---------------- static device scratch (no runtime alloc) ----------------
__device__ float4             g_boxes[NTOT];        // decoded clipped boxes, [a*HW+pix]
__device__ unsigned           g_sbits[NTOT];        // score bits (0 if invalid)
__device__ unsigned           g_hist[HIST_SZ];
__device__ unsigned long long g_cand[CAP];          // key64 = sbits<<32 | (0xFFFFFFFF - n)
__device__ unsigned           g_ccount;
__device__ unsigned           g_T;                  // threshold histogram bin
__device__ float4             g_top_boxes[PRE_N];
__device__ unsigned long long g_invalid[MASK_W];
__device__ unsigned long long g_mask[(size_t)PRE_N * MASK_W];

// 9 base anchors (ratios 0.5,1,2 x scales 8,16,32), numpy semantics:
// r=0.5 -> (ws,hs)=(23,12); r=1 -> (16,16); r=2 -> (11,22).
__constant__ float4 c_anchors[AA] = {
    { -84.f,  -40.f,  99.f,  55.f},   // r=0.5 s=8
    {-176.f,  -88.f, 191.f, 103.f},   // r=0.5 s=16
    {-360.f, -184.f, 375.f, 199.f},   // r=0.5 s=32
    { -56.f,  -56.f,  71.f,  71.f},   // r=1   s=8
    {-120.f, -120.f, 135.f, 135.f},   // r=1   s=16
    {-248.f, -248.f, 263.f, 263.f},   // r=1   s=32
    { -36.f,  -80.f,  51.f,  95.f},   // r=2   s=8
    { -80.f, -168.f,  95.f, 183.f},   // r=2   s=16
    {-168.f, -344.f, 183.f, 359.f}    // r=2   s=32
};

// ---------------- K1: clear scratch ----------------
__global__ void k_clear() {
    unsigned t = blockIdx.x * blockDim.x + threadIdx.x;   // 65536 threads
    if (t < HIST_SZ) g_hist[t] = 0u;
    if (t < CAP)     g_cand[t] = 0ull;
    if (t < MASK_W)  g_invalid[t] = 0ull;
    if (t == 0)      g_ccount = 0u;
}

// ---------------- K2: decode boxes + score-bit histogram ----------------
__global__ void k_decode(const float* __restrict__ scores,
                         const float* __restrict__ deltas,
                         const float* __restrict__ im_info) {
    int t = blockIdx.x * blockDim.x + threadIdx.x;
    if (t >= NTOT) return;
    int a   = t / HW;        // channel-major thread mapping -> coalesced loads
    int pix = t % HW;

    float sc = __ldg(&scores[(AA + a) * HW + pix]);       // fg score
    float dx = __ldg(&deltas[(4 * a + 0) * HW + pix]);
    float dy = __ldg(&deltas[(4 * a + 1) * HW + pix]);
    float dw = __ldg(&deltas[(4 * a + 2) * HW + pix]);
    float dh = __ldg(&deltas[(4 * a + 3) * HW + pix]);
    dw = fminf(fmaxf(dw, -10.f), 10.f);
    dh = fminf(fmaxf(dh, -10.f), 10.f);

    int x = pix % WW, y = pix / WW;
    float4 an = c_anchors[a];
    float ax1 = an.x + 16.f * x, ay1 = an.y + 16.f * y;
    float ax2 = an.z + 16.f * x, ay2 = an.w + 16.f * y;
    float wdt = ax2 - ax1 + 1.f, hgt = ay2 - ay1 + 1.f;
    float cx  = ax1 + 0.5f * wdt, cy = ay1 + 0.5f * hgt;

    float pcx = dx * wdt + cx;
    float pcy = dy * hgt + cy;
    float pw  = expf(dw) * wdt;
    float ph  = expf(dh) * hgt;

    float imh = __ldg(&im_info[0]), imw = __ldg(&im_info[1]), iscale = __ldg(&im_info[2]);
    float x1 = fminf(fmaxf(pcx - 0.5f * pw, 0.f), imw - 1.f);
    float y1 = fminf(fmaxf(pcy - 0.5f * ph, 0.f), imh - 1.f);
    float x2 = fminf(fmaxf(pcx + 0.5f * pw, 0.f), imw - 1.f);
    float y2 = fminf(fmaxf(pcy + 0.5f * ph, 0.f), imh - 1.f);

    float min_sz = 16.f * iscale;
    bool valid = (x2 - x1 + 1.f >= min_sz) && (y2 - y1 + 1.f >= min_sz);

    g_boxes[t] = make_float4(x1, y1, x2, y2);
    unsigned sb = (valid && sc > 0.f) ? __float_as_uint(sc) : 0u;
    g_sbits[t] = sb;
    atomicAdd(&g_hist[sb >> (32 - HIST_BITS)], 1u);
}

// ---------------- K3: find threshold bin (top-6000 boundary) ----------------
__global__ void k_thresh() {
    __shared__ unsigned csum[1024];
    const int CHUNK = HIST_SZ / 1024;   // 64
    int tid = threadIdx.x;
    unsigned s = 0;
    int base = tid * CHUNK;
    for (int i = 0; i < CHUNK; i++) s += g_hist[base + i];
    csum[tid] = s;
    __syncthreads();
    if (tid == 0) {
        unsigned acc = 0;
        int c;
        for (c = 1023; c >= 0; c--) {
            if (acc + csum[c] >= PRE_N) break;
            acc += csum[c];
        }
        unsigned T = 0;
        if (c >= 0) {
            int b;
            for (b = c * CHUNK + CHUNK - 1; b >= c * CHUNK; b--) {
                acc += g_hist[b];
                if (acc >= PRE_N) break;
            }
            if (b < c * CHUNK) b = c * CHUNK;
            T = (unsigned)b;
        }
        g_T = T;
    }
}

// ---------------- K4: compact candidates >= threshold bin ----------------
__global__ void k_compact() {
    int t = blockIdx.x * blockDim.x + threadIdx.x;
    if (t >= NTOT) return;
    unsigned sb = g_sbits[t];
    if (sb != 0u && (sb >> (32 - HIST_BITS)) >= g_T) {
        unsigned p = atomicAdd(&g_ccount, 1u);
        if (p < CAP) {
            int a = t / HW, pix = t % HW;
            unsigned n = (unsigned)(pix * AA + a);   // reference flat index
            g_cand[p] = ((unsigned long long)sb << 32) | (0xFFFFFFFFu - n);
        }
    }
}

// ---------------- K5: per-block bitonic sort of 4096 keys in smem ----------------
// block 0 sorts [0,4096) ascending, block 1 sorts [4096,8192) descending
// -> concatenation is a single bitonic sequence for the final merge.
__global__ void k_sort_local() {
    __shared__ unsigned long long s[HALF];
    int tid = threadIdx.x;
    int base = blockIdx.x * HALF;
    bool asc = (blockIdx.x == 0);
    for (int i = tid; i < HALF; i += 1024) s[i] = g_cand[base + i];
    __syncthreads();
    for (int k = 2; k <= HALF; k <<= 1) {
        for (int j = k >> 1; j > 0; j >>= 1) {
            for (int i = tid; i < HALF; i += 1024) {
                int ixj = i ^ j;
                if (ixj > i) {
                    bool region_asc = (((i & k) == 0) == asc);
                    unsigned long long va = s[i], vb = s[ixj];
                    if (region_asc ? (va > vb) : (va < vb)) { s[i] = vb; s[ixj] = va; }
                }
            }
            __syncthreads();
        }
    }
    for (int i = tid; i < HALF; i += 1024) g_cand[base + i] = s[i];
}

// ---------------- K6: final bitonic merge (descending) + gather ----------------
// Each block loads both halves, applies the j=4096 exchange, keeps its half,
// finishes the merge in smem, then directly emits g_top_boxes / g_invalid.
__global__ void k_merge() {
    __shared__ unsigned long long s[HALF];
    int tid = threadIdx.x;
    int b = blockIdx.x;
    for (int i = tid; i < HALF; i += 1024) {
        unsigned long long lo = g_cand[i];
        unsigned long long hi = g_cand[i + HALF];
        s[i] = (b == 0) ? (lo > hi ? lo : hi) : (lo > hi ? hi : lo);
    }
    __syncthreads();
    for (int j = HALF >> 1; j > 0; j >>= 1) {
        for (int i = tid; i < HALF; i += 1024) {
            int ixj = i ^ j;
            if (ixj > i) {
                unsigned long long va = s[i], vb = s[ixj];
                if (va < vb) { s[i] = vb; s[ixj] = va; }   // descending
            }
        }
        __syncthreads();
    }
    int rbase = b * HALF;
    for (int i = tid; i < HALF; i += 1024) {
        int r = rbase + i;
        if (r >= PRE_N) break;
        unsigned long long key = s[i];
        unsigned sb = (unsigned)(key >> 32);
        if (sb == 0u) {
            atomicOr(&g_invalid[r >> 6], 1ull << (r & 63));
            g_top_boxes[r] = make_float4(0.f, 0.f, 0.f, 0.f);
        } else {
            unsigned n = 0xFFFFFFFFu - (unsigned)key;
            int a = n % AA, pix = n / AA;
            g_top_boxes[r] = g_boxes[a * HW + pix];
        }
    }
}

// ---------------- K7: 6000x6000 IoU suppression bitmask ----------------
__global__ void k_mask() {
    __shared__ float4 col[64];
    int cb = blockIdx.x, rb = blockIdx.y;
    int t = threadIdx.x;
    int c0 = cb * 64;
    col[t] = (c0 + t < PRE_N) ? g_top_boxes[c0 + t] : make_float4(0.f, 0.f, 0.f, 0.f);
    __syncthreads();
    int row = rb * 64 + t;
    if (row >= PRE_N) return;
    float4 rbx = g_top_boxes[row];
    float rarea = (rbx.z - rbx.x) * (rbx.w - rbx.y);
    unsigned long long bits = 0ull;
    int ncols = min(64, PRE_N - c0);
    #pragma unroll 4
    for (int c = 0; c < ncols; c++) {
        float4 cbx = col[c];
        float xx1 = fmaxf(rbx.x, cbx.x), yy1 = fmaxf(rbx.y, cbx.y);
        float xx2 = fminf(rbx.z, cbx.z), yy2 = fminf(rbx.w, cbx.w);
        float w = fmaxf(xx2 - xx1, 0.f), h = fmaxf(yy2 - yy1, 0.f);
        float inter = w * h;
        float carea = (cbx.z - cbx.x) * (cbx.w - cbx.y);
        float iou = inter / (rarea + carea - inter);
        if (iou > NMS_TH) bits |= (1ull << c);
    }
    g_mask[(size_t)row * MASK_W + cb] = bits;
}

// ---------------- K8: serial greedy NMS (1 warp, register mask) + output ----------------
__global__ void k_nms_out(float* __restrict__ out) {
    __shared__ int kept[POST_N];
    int l = threadIdx.x;

    // lane l owns mask words l, l+32, l+64 (lanes 30,31 have no third word)
    unsigned long long s0 = g_invalid[l];
    unsigned long long s1 = g_invalid[l + 32];
    unsigned long long s2 = (l < 30) ? g_invalid[l + 64] : ~0ull;
    if (l == 29) s2 |= ~((1ull << 48) - 1ull);   // word 93: bits 6000..6015 invalid

    int cnt = 0;
    while (cnt < POST_N) {
        unsigned long long c0 = ~s0, c1 = ~s1, c2 = ~s2;
        unsigned cand;
        if (c0)      cand = (unsigned)((l << 6)        + __ffsll((long long)c0) - 1);
        else if (c1) cand = (unsigned)(((l + 32) << 6) + __ffsll((long long)c1) - 1);
        else if (c2) cand = (unsigned)(((l + 64) << 6) + __ffsll((long long)c2) - 1);
        else         cand = 0x7FFFFFFFu;
        unsigned i = __reduce_min_sync(0xFFFFFFFFu, cand);
        if (i >= PRE_N) break;

        if (l == 0) kept[cnt] = (int)i;
        cnt++;

        const unsigned long long* row = g_mask + (size_t)i * MASK_W;
        s0 |= row[l];                       // coalesced
        s1 |= row[l + 32];
        if (l < 30) s2 |= row[l + 64];
        // diagonal bit of row i is set (self-IoU = 1), so bit i is now suppressed
    }
    __syncwarp();

    for (int r = l; r < POST_N; r += 32) {
        float4 b4 = (r < cnt) ? g_top_boxes[kept[r]] : make_float4(0.f, 0.f, 0.f, 0.f);
        out[r * 5 + 0] = 0.f;
        out[r * 5 + 1] = b4.x;
        out[r * 5 + 2] = b4.y;
        out[r * 5 + 3] = b4.z;
        out[r * 5 + 4] = b4.w;
    }
}

// ---------------- launch ----------------
extern "C" void kernel_launch(void* const* d_in, const int* in_sizes, int n_in,
                              void* d_out, int out_size) {
    const float* scores  = (const float*)d_in[0];
    const float* deltas  = (const float*)d_in[1];
    const float* im_info = (const float*)d_in[2];
    float* out = (float*)d_out;
    (void)in_sizes; (void)n_in; (void)out_size;

    k_clear     <<<HIST_SZ / 1024, 1024>>>();
    k_decode    <<<(NTOT + 255) / 256, 256>>>(scores, deltas, im_info);
    k_thresh    <<<1, 1024>>>();
    k_compact   <<<(NTOT + 255) / 256, 256>>>();
    k_sort_local<<<2, 1024>>>();
    k_merge     <<<2, 1024>>>();
    k_mask      <<<dim3(MASK_W, MASK_W), 64>>>();
    k_nms_out   <<<1, 32>>>(out);
}

// round 13
// speedup vs baseline: 1.0638x; 1.0638x over previous
#include <cuda_runtime.h>
#include <cuda_bf16.h>

// ---------------- problem constants ----------------
#define AA        9
#define HH        128
#define WW        192
#define HW        (HH * WW)          // 24576
#define NTOT      (HW * AA)          // 221184
#define PRE_N     6000
#define POST_N    300
#define MASK_W    94                 // ceil(6000/64)
#define CAP       8192               // candidate capacity (power of 2 for bitonic)
#define HALF      4096
#define HIST_BITS 16
#define HIST_SZ   (1u << HIST_BITS)
#define NMS_TH    0.7f
#define AMB_CAP   1024

// ---------------- static device scratch (no runtime alloc) ----------------
// Pipeline is self-cleaning: every array is either fully overwritten each run,
// zeroed by an earlier kernel in the same run, or provably garbage-tolerant
// (g_mask lower triangle). Static arrays start zeroed at module load.
__device__ float4             g_boxes[NTOT];        // decoded clipped boxes, [a*HW+pix]
__device__ unsigned           g_sbits[NTOT];        // score bits (0 if invalid)
__device__ unsigned           g_hist[HIST_SZ];      // zeroed by k_thresh after use
__device__ unsigned long long g_cand[CAP];          // zeroed by k_decode
__device__ unsigned           g_ccount;             // zeroed by k_decode
__device__ unsigned           g_T;                  // threshold histogram bin
__device__ float4             g_top_boxes[PRE_N];   // fully overwritten by k_sort_merge
__device__ unsigned long long g_invalid[MASK_W];    // zeroed by k_decode
__device__ unsigned long long g_mask[(size_t)PRE_N * MASK_W];  // garbage-tolerant below diag
__device__ unsigned           g_amb_count;          // zeroed by k_decode
__device__ unsigned           g_amb[AMB_CAP];
__device__ unsigned           g_bar;                // 2-block barrier, zeroed by k_decode

// 9 base anchors (ratios 0.5,1,2 x scales 8,16,32), numpy semantics:
// r=0.5 -> (ws,hs)=(23,12); r=1 -> (16,16); r=2 -> (11,22).
__constant__ float4 c_anchors[AA] = {
    { -84.f,  -40.f,  99.f,  55.f},   // r=0.5 s=8
    {-176.f,  -88.f, 191.f, 103.f},   // r=0.5 s=16
    {-360.f, -184.f, 375.f, 199.f},   // r=0.5 s=32
    { -56.f,  -56.f,  71.f,  71.f},   // r=1   s=8
    {-120.f, -120.f, 135.f, 135.f},   // r=1   s=16
    {-248.f, -248.f, 263.f, 263.f},   // r=1   s=32
    { -36.f,  -80.f,  51.f,  95.f},   // r=2   s=8
    { -80.f, -168.f,  95.f, 183.f},   // r=2   s=16
    {-168.f, -344.f, 183.f, 359.f}    // r=2   s=32
};

// ---------------- K2: decode (4 pix/thread, float4) + histogram + scratch clear ----
__global__ void k_decode(const float* __restrict__ scores,
                         const float* __restrict__ deltas,
                         const float* __restrict__ im_info) {
    int v = blockIdx.x * blockDim.x + threadIdx.x;   // 0 .. NTOT/4-1

    // fold the small scratch clears into this big launch (arrays consumed later)
    if (v < CAP)    g_cand[v] = 0ull;
    if (v < MASK_W) g_invalid[v] = 0ull;
    if (v == 0)     { g_ccount = 0u; g_amb_count = 0u; g_bar = 0u; }

    if (v >= NTOT / 4) return;
    int t0   = v * 4;
    int a    = t0 / HW;          // HW multiple of 4 -> all 4 elems same anchor
    int pix0 = t0 % HW;          // multiple of 4; WW=192 divisible by 4 -> same row
    int y = pix0 / WW, x0 = pix0 % WW;

    float4 scv = *(const float4*)&scores[(AA + a) * HW + pix0];
    float4 dxv = *(const float4*)&deltas[(4 * a + 0) * HW + pix0];
    float4 dyv = *(const float4*)&deltas[(4 * a + 1) * HW + pix0];
    float4 dwv = *(const float4*)&deltas[(4 * a + 2) * HW + pix0];
    float4 dhv = *(const float4*)&deltas[(4 * a + 3) * HW + pix0];

    float imh = __ldg(&im_info[0]), imw = __ldg(&im_info[1]), iscale = __ldg(&im_info[2]);
    float min_sz = 16.f * iscale;

    float4 an = c_anchors[a];
    float wdt = an.z - an.x + 1.f, hgt = an.w - an.y + 1.f;   // shift-invariant
    float cy  = an.y + 16.f * y + 0.5f * hgt;
    float cx0 = an.x + 0.5f * wdt;

    float scs[4] = {scv.x, scv.y, scv.z, scv.w};
    float dxs[4] = {dxv.x, dxv.y, dxv.z, dxv.w};
    float dys[4] = {dyv.x, dyv.y, dyv.z, dyv.w};
    float dws[4] = {dwv.x, dwv.y, dwv.z, dwv.w};
    float dhs[4] = {dhv.x, dhv.y, dhv.z, dhv.w};
    unsigned sbo[4];

    #pragma unroll
    for (int e = 0; e < 4; e++) {
        float dw = fminf(fmaxf(dws[e], -10.f), 10.f);
        float dh = fminf(fmaxf(dhs[e], -10.f), 10.f);
        float cx = cx0 + 16.f * (x0 + e);

        float pcx = dxs[e] * wdt + cx;
        float pcy = dys[e] * hgt + cy;
        float pw  = expf(dw) * wdt;
        float ph  = expf(dh) * hgt;

        float x1 = fminf(fmaxf(pcx - 0.5f * pw, 0.f), imw - 1.f);
        float y1 = fminf(fmaxf(pcy - 0.5f * ph, 0.f), imh - 1.f);
        float x2 = fminf(fmaxf(pcx + 0.5f * pw, 0.f), imw - 1.f);
        float y2 = fminf(fmaxf(pcy + 0.5f * ph, 0.f), imh - 1.f);

        bool valid = (x2 - x1 + 1.f >= min_sz) && (y2 - y1 + 1.f >= min_sz);

        g_boxes[t0 + e] = make_float4(x1, y1, x2, y2);
        unsigned sb = (valid && scs[e] > 0.f) ? __float_as_uint(scs[e]) : 0u;
        sbo[e] = sb;
        atomicAdd(&g_hist[sb >> (32 - HIST_BITS)], 1u);
    }
    ((uint4*)g_sbits)[v] = make_uint4(sbo[0], sbo[1], sbo[2], sbo[3]);
}

// ---------------- K3: find threshold bin, then zero the histogram ----------------
__global__ void k_thresh() {
    __shared__ unsigned csum[1024];
    const int CHUNK = HIST_SZ / 1024;   // 64
    int tid = threadIdx.x;
    unsigned s = 0;
    int base = tid * CHUNK;
    for (int i = 0; i < CHUNK; i++) s += g_hist[base + i];
    csum[tid] = s;
    __syncthreads();
    if (tid == 0) {
        unsigned acc = 0;
        int c;
        for (c = 1023; c >= 0; c--) {
            if (acc + csum[c] >= PRE_N) break;
            acc += csum[c];
        }
        unsigned T = 0;
        if (c >= 0) {
            int b;
            for (b = c * CHUNK + CHUNK - 1; b >= c * CHUNK; b--) {
                acc += g_hist[b];
                if (acc >= PRE_N) break;
            }
            if (b < c * CHUNK) b = c * CHUNK;
            T = (unsigned)b;
        }
        g_T = T;
    }
    __syncthreads();                     // fine scan above must finish first
    uint4 z = make_uint4(0u, 0u, 0u, 0u);
    uint4* hv = (uint4*)&g_hist[base];
    #pragma unroll
    for (int i = 0; i < CHUNK / 4; i++) hv[i] = z;   // clean for next replay
}

// ---------------- K4: compact candidates >= threshold bin (uint4-vectorized) ----------
__global__ void k_compact() {
    int v = blockIdx.x * blockDim.x + threadIdx.x;
    if (v >= NTOT / 4) return;
    uint4 sbv = ((const uint4*)g_sbits)[v];
    unsigned T = g_T;
    unsigned sbs[4] = {sbv.x, sbv.y, sbv.z, sbv.w};
    #pragma unroll
    for (int e = 0; e < 4; e++) {
        unsigned sb = sbs[e];
        if (sb != 0u && (sb >> (32 - HIST_BITS)) >= T) {
            unsigned p = atomicAdd(&g_ccount, 1u);
            if (p < CAP) {
                int t = 4 * v + e;
                int a = t / HW, pix = t % HW;
                unsigned n = (unsigned)(pix * AA + a);   // reference flat index
                g_cand[p] = ((unsigned long long)sb << 32) | (0xFFFFFFFFu - n);
            }
        }
    }
}

// ---------------- K5: fused sort (2 blocks, smem) + device barrier + merge + gather --
// Phase 1: block 0 sorts [0,4096) ascending, block 1 sorts [4096,8192) descending
//          -> concatenation is a single bitonic sequence.
// Barrier: grid=2, both blocks trivially co-resident -> spin barrier is safe.
// Phase 2: each block applies the j=4096 exchange, finishes the descending merge
//          of its half in smem, then emits g_top_boxes / g_invalid directly.
__global__ void __launch_bounds__(1024, 1) k_sort_merge() {
    __shared__ unsigned long long s[HALF];
    int tid = threadIdx.x;
    int b = blockIdx.x;
    int base = b * HALF;
    bool asc = (b == 0);

    // ---- phase 1: local bitonic sort in smem ----
    for (int i = tid; i < HALF; i += 1024) s[i] = g_cand[base + i];
    __syncthreads();
    for (int k = 2; k <= HALF; k <<= 1) {
        for (int j = k >> 1; j > 0; j >>= 1) {
            for (int i = tid; i < HALF; i += 1024) {
                int ixj = i ^ j;
                if (ixj > i) {
                    bool region_asc = (((i & k) == 0) == asc);
                    unsigned long long va = s[i], vb = s[ixj];
                    if (region_asc ? (va > vb) : (va < vb)) { s[i] = vb; s[ixj] = va; }
                }
            }
            __syncthreads();
        }
    }
    for (int i = tid; i < HALF; i += 1024) g_cand[base + i] = s[i];

    // ---- inter-block barrier (release/acquire) ----
    __syncthreads();
    __threadfence();
    if (tid == 0) {
        atomicAdd(&g_bar, 1u);
        while (atomicAdd(&g_bar, 0u) < 2u) { __nanosleep(32); }
    }
    __syncthreads();
    __threadfence();

    // ---- phase 2: cross-half exchange + finish descending merge ----
    for (int i = tid; i < HALF; i += 1024) {
        unsigned long long lo = g_cand[i];
        unsigned long long hi = g_cand[i + HALF];
        s[i] = (b == 0) ? (lo > hi ? lo : hi) : (lo > hi ? hi : lo);
    }
    __syncthreads();
    for (int j = HALF >> 1; j > 0; j >>= 1) {
        for (int i = tid; i < HALF; i += 1024) {
            int ixj = i ^ j;
            if (ixj > i) {
                unsigned long long va = s[i], vb = s[ixj];
                if (va < vb) { s[i] = vb; s[ixj] = va; }   // descending
            }
        }
        __syncthreads();
    }

    // ---- gather top-6000 boxes for this rank range ----
    int rbase = b * HALF;
    for (int i = tid; i < HALF; i += 1024) {
        int r = rbase + i;
        if (r >= PRE_N) break;
        unsigned long long key = s[i];
        unsigned sb = (unsigned)(key >> 32);
        if (sb == 0u) {
            atomicOr(&g_invalid[r >> 6], 1ull << (r & 63));
            g_top_boxes[r] = make_float4(0.f, 0.f, 0.f, 0.f);
        } else {
            unsigned n = 0xFFFFFFFFu - (unsigned)key;
            int a = n % AA, pix = n / AA;
            g_top_boxes[r] = g_boxes[a * HW + pix];
        }
    }
}

// ---------------- K7: IoU suppression bitmask, upper triangle only, division-free ----
// Greedy-scan invariant: when candidate i is selected every bit < i is already
// set in the state, and garbage words w < i>>6 cover only columns < i, so OR-ing
// uninitialized/stale lower-triangle words is harmless -> cb<rb blocks write NOTHING.
// Decision: RN(inter/den) > 0.7f  <=>  inter >= (0.7f + 2^-25)*den (exact reals).
// cheap = fma(-0.7f, den, inter), err <= 2^-24|cheap|; s = 2^-25*den exact.
// Band pairs -> fixup list, resolved with the reference's own fp32 division.
__global__ void k_mask() {
    __shared__ float4 col[64];
    __shared__ float  carea_s[64];
    int cb = blockIdx.x, rb = blockIdx.y;
    if (cb < rb) return;                   // lower triangle never influences the scan
    int t = threadIdx.x;
    int row = rb * 64 + t;
    int c0 = cb * 64;
    int ci = c0 + t;
    float4 cv = (ci < PRE_N) ? __ldg(&g_top_boxes[ci]) : make_float4(0.f, 0.f, 0.f, 0.f);
    col[t] = cv;
    carea_s[t] = (cv.z - cv.x) * (cv.w - cv.y);
    __syncthreads();
    if (row >= PRE_N) return;
    float4 rbx = __ldg(&g_top_boxes[row]);
    float rarea = (rbx.z - rbx.x) * (rbx.w - rbx.y);
    unsigned long long bits = 0ull;
    int ncols = min(64, PRE_N - c0);
    #pragma unroll 4
    for (int c = 0; c < ncols; c++) {
        float4 cbx = col[c];
        float xx1 = fmaxf(rbx.x, cbx.x), yy1 = fmaxf(rbx.y, cbx.y);
        float xx2 = fminf(rbx.z, cbx.z), yy2 = fminf(rbx.w, cbx.w);
        float w = fmaxf(xx2 - xx1, 0.f), h = fmaxf(yy2 - yy1, 0.f);
        float inter = w * h;
        float den   = (rarea + carea_s[c]) - inter;
        float cheap = fmaf(-NMS_TH, den, inter);
        float s     = 0x1p-25f * den;
        bool cond   = (den > 0.f) && (cheap > s);
        float margin = fmaf(0x1p-23f, fabsf(cheap), 0x1p-30f * den);
        if (den > 0.f && fabsf(cheap - s) <= margin) {
            unsigned p = atomicAdd(&g_amb_count, 1u);
            if (p < AMB_CAP) g_amb[p] = (unsigned)row * 8192u + (unsigned)(c0 + c);
        }
        if (cond) bits |= (1ull << c);
    }
    g_mask[(size_t)row * MASK_W + cb] = bits;
}

// ---------------- K8: fixup + serial greedy NMS (1 warp, register mask) + output ----
__device__ __forceinline__ void prefetch_rows(int i, int l) {
    // prefetch the 6 cache lines of each of rows i+1..i+10 into L1
    // (60 line×row pairs spread over lanes 0..29, two prefetches per lane)
    if (l < 30) {
        #pragma unroll
        for (int k = 0; k < 2; k++) {
            int p = l + 30 * k;                 // 0..59
            int d = 1 + p / 6;                  // 1..10
            int line = p % 6;                   // 0..5
            int r2 = i + d;
            if (r2 < PRE_N) {
                const char* ptr = (const char*)(g_mask + (size_t)r2 * MASK_W) + line * 128;
                asm volatile("prefetch.global.L1 [%0];" :: "l"(ptr));
            }
        }
    }
}

__global__ void __launch_bounds__(32, 1) k_nms_out(float* __restrict__ out) {
    __shared__ int kept[POST_N];
    int l = threadIdx.x;

    // resolve ambiguous IoU pairs with the reference's exact fp32 division
    unsigned namb = g_amb_count;
    if (namb > AMB_CAP) namb = AMB_CAP;
    for (unsigned e = l; e < namb; e += 32) {
        unsigned pk = g_amb[e];
        int row = (int)(pk / 8192u), colk = (int)(pk % 8192u);
        float4 rbx = g_top_boxes[row];
        float4 cbx = g_top_boxes[colk];
        float rarea = (rbx.z - rbx.x) * (rbx.w - rbx.y);
        float carea = (cbx.z - cbx.x) * (cbx.w - cbx.y);
        float xx1 = fmaxf(rbx.x, cbx.x), yy1 = fmaxf(rbx.y, cbx.y);
        float xx2 = fminf(rbx.z, cbx.z), yy2 = fminf(rbx.w, cbx.w);
        float w = fmaxf(xx2 - xx1, 0.f), h = fmaxf(yy2 - yy1, 0.f);
        float inter = w * h;
        float den   = (rarea + carea) - inter;
        float iou   = __fdiv_rn(inter, den);
        unsigned long long bit = 1ull << (colk & 63);
        unsigned long long* word = &g_mask[(size_t)row * MASK_W + (colk >> 6)];
        if (iou > NMS_TH) atomicOr(word, bit);
        else              atomicAnd(word, ~bit);
    }
    // Order fixup RMWs (L2) before any L1 prefetch/__ldg of mask lines:
    // __syncwarp alone orders execution, not memory visibility.
    __threadfence_block();
    __syncwarp();

    prefetch_rows(-1, l);   // warm rows 0..9

    // lane l owns mask words l, l+32, l+64 (lanes 30,31 have no third word)
    unsigned long long s0 = g_invalid[l];
    unsigned long long s1 = g_invalid[l + 32];
    unsigned long long s2 = (l < 30) ? g_invalid[l + 64] : ~0ull;
    if (l == 29) s2 |= ~((1ull << 48) - 1ull);   // word 93: bits 6000..6015 invalid

    int cnt = 0;
    while (cnt < POST_N) {
        unsigned long long c0 = ~s0, c1 = ~s1, c2 = ~s2;
        unsigned cand;
        if (c0)      cand = (unsigned)((l << 6)        + __ffsll((long long)c0) - 1);
        else if (c1) cand = (unsigned)(((l + 32) << 6) + __ffsll((long long)c1) - 1);
        else if (c2) cand = (unsigned)(((l + 64) << 6) + __ffsll((long long)c2) - 1);
        else         cand = 0x7FFFFFFFu;
        unsigned i = __reduce_min_sync(0xFFFFFFFFu, cand);
        if (i >= PRE_N) break;

        if (l == 0) kept[cnt] = (int)i;
        cnt++;

        prefetch_rows((int)i, l);           // hide next rows' L2 latency

        const unsigned long long* row = g_mask + (size_t)i * MASK_W;
        s0 |= __ldg(&row[l]);               // coalesced, read-only path (L1-resident)
        s1 |= __ldg(&row[l + 32]);
        if (l < 30) s2 |= __ldg(&row[l + 64]);
        // diagonal bit of row i is set (self-IoU = 1), so bit i is now suppressed
    }
    __syncwarp();

    for (int r = l; r < POST_N; r += 32) {
        float4 b4 = (r < cnt) ? g_top_boxes[kept[r]] : make_float4(0.f, 0.f, 0.f, 0.f);
        out[r * 5 + 0] = 0.f;
        out[r * 5 + 1] = b4.x;
        out[r * 5 + 2] = b4.y;
        out[r * 5 + 3] = b4.z;
        out[r * 5 + 4] = b4.w;
    }
}

// ---------------- launch ----------------
extern "C" void kernel_launch(void* const* d_in, const int* in_sizes, int n_in,
                              void* d_out, int out_size) {
    const float* scores  = (const float*)d_in[0];
    const float* deltas  = (const float*)d_in[1];
    const float* im_info = (const float*)d_in[2];
    float* out = (float*)d_out;
    (void)in_sizes; (void)n_in; (void)out_size;

    k_decode    <<<(NTOT / 4 + 255) / 256, 256>>>(scores, deltas, im_info);
    k_thresh    <<<1, 1024>>>();
    k_compact   <<<(NTOT / 4 + 255) / 256, 256>>>();
    k_sort_merge<<<2, 1024>>>();
    k_mask      <<<dim3(MASK_W, MASK_W), 64>>>();
    k_nms_out   <<<1, 32>>>(out);
}